// round 17
// baseline (speedup 1.0000x reference)
#include <cuda_runtime.h>
#include <cuda_bf16.h>

#define BATCH 8
#define NBOX 2048
#define MAXDET 100
#define THREADS 512
#define EPT 4                       // sort: elements per thread (blocked)
#define MIN_SIZE 25.0f
#define SCORE_THR 0.001f
#define CIOU 0.23076923f            // 0.3/1.3 : iou>0.3 <=> inter > CIOU*(A+B)
#define FULL 0xffffffffu

typedef unsigned long long u64;
typedef unsigned int u32;

// key: (score bits << 32) | ~idx  -> descending sort == (score desc, idx asc)
__device__ __forceinline__ u64 pack_si(float s, int idx) {
    return ((u64)__float_as_uint(s) << 32) | (u32)(~idx);
}
__device__ __forceinline__ float ciou_area(float4 b) {
    return CIOU * ((b.z - b.x) * (b.w - b.y));
}
__device__ __forceinline__ float inter_of(float4 a, float4 b) {
    float ix = fminf(a.z, b.z) - fmaxf(a.x, b.x);
    float iy = fminf(a.w, b.w) - fmaxf(a.y, b.y);
    return fmaxf(ix, 0.f) * fmaxf(iy, 0.f);
}

extern __shared__ char smem_raw[];
// sbox f4[2048] | skey u64[2048] | pbox f4[100] | pca f[100]
// sdead u32[2][8] | sacc3 u32[4] | smat8 u8[2][128] | xmat8 u8[3][128]
#define OFF_PBOX  (32768 + 16384)
#define OFF_PCA   (OFF_PBOX + 1600)
#define OFF_SDEAD (OFF_PCA + 400)
#define OFF_SACC  (OFF_SDEAD + 64)
#define OFF_SMAT  (OFF_SACC + 16)
#define OFF_XMAT  (OFF_SMAT + 256)
#define SMEM_BYTES (OFF_XMAT + 384 + 64)

__global__ __launch_bounds__(THREADS, 1)
void nms_kernel(const float* __restrict__ boxes,
                const float* __restrict__ scores,
                float* __restrict__ out,
                int write_mask)
{
    float4* sbox = (float4*)smem_raw;
    u64*    skey = (u64*)(sbox + NBOX);
    float4* pbox = (float4*)(smem_raw + OFF_PBOX);
    float*  pca  = (float*)(smem_raw + OFF_PCA);
    u32*    sdead = (u32*)(smem_raw + OFF_SDEAD);     // [2][8]
    u32*    sacc3 = (u32*)(smem_raw + OFF_SACC);      // [3]
    unsigned char* smat8 = (unsigned char*)(smem_raw + OFF_SMAT);  // [2][128]
    unsigned char* xmat8 = (unsigned char*)(smem_raw + OFF_XMAT);  // [3][128]

    const int img  = blockIdx.x;
    const int tid  = threadIdx.x;
    const int warp = tid >> 5;
    const int lane = tid & 31;
    const int base = tid * EPT;

    // ---- coalesced load, validity filter, keys to shared ----
    const float4* bp = (const float4*)(boxes + (size_t)img * NBOX * 4);
    const float*  sp = scores + (size_t)img * NBOX;
    #pragma unroll
    for (int p = 0; p < NBOX / THREADS; p++) {
        int i = p * THREADS + tid;               // coalesced
        float4 b = bp[i];
        float  s = sp[i];
        float w = b.z - b.x;
        float h = b.w - b.y;
        bool valid = (w >= MIN_SIZE) && (h >= MIN_SIZE) && (s >= SCORE_THR);
        sbox[i] = b;
        skey[i] = valid ? pack_si(s, i) : 0ULL;
    }

    // ---- init output padding + pipeline buffers ----
    float* outr = out + (size_t)img * MAXDET * 5;
    float* outm = out + (size_t)BATCH * MAXDET * 5 + (size_t)img * MAXDET;
    for (int i = tid; i < MAXDET; i += THREADS) {
        outr[i * 5 + 0] = (float)img;
        outr[i * 5 + 1] = 0.f;
        outr[i * 5 + 2] = 0.f;
        outr[i * 5 + 3] = 0.f;
        outr[i * 5 + 4] = 0.f;
        if (write_mask) outm[i] = 0.f;
    }
    if (tid < 3) sacc3[tid] = 0;
    __syncthreads();

    // blocked ownership for the sort
    u64 val[EPT];
    #pragma unroll
    for (int e = 0; e < EPT; e++) val[e] = skey[base + e];

    // ================= bitonic sort (descending) =============================
    // presort k=2..4 entirely in registers
    #pragma unroll
    for (int k = 2; k <= 4; k <<= 1) {
        #pragma unroll
        for (int j = k >> 1; j > 0; j >>= 1) {
            #pragma unroll
            for (int e = 0; e < EPT; e++) {
                if ((e & j) == 0) {
                    int f = e | j;
                    bool up = (((base + e) & k) == 0);
                    u64 x = val[e], y = val[f];
                    bool sw = up ? (x < y) : (x > y);
                    if (sw) { val[e] = y; val[f] = x; }
                }
            }
        }
    }

    #pragma unroll 1
    for (int kk = 8; kk <= NBOX; kk <<= 1) {
        const bool dir = ((base & kk) == 0);

        // shared stages: j in {1024..128}
        #pragma unroll 1
        for (int j = kk >> 1; j >= 128; j >>= 1) {
            #pragma unroll
            for (int e = 0; e < EPT; e++) skey[base + e] = val[e];
            __syncthreads();
            bool iLow = ((tid & (j >> 2)) == 0);
            int pbase = base ^ j;
            #pragma unroll
            for (int e = 0; e < EPT; e++) {
                u64 o = skey[pbase + e];
                u64 mx = val[e] > o ? val[e] : o;
                u64 mn = val[e] > o ? o : val[e];
                val[e] = (iLow == dir) ? mx : mn;
            }
            __syncthreads();
        }
        // shfl stages: j in {64..4}
        {
            int jhi = (kk >> 1) > 64 ? 64 : (kk >> 1);
            #pragma unroll 1
            for (int j = jhi; j >= 4; j >>= 1) {
                int jl = j >> 2;
                bool iLow = ((tid & jl) == 0);
                #pragma unroll
                for (int e = 0; e < EPT; e++) {
                    u64 o = __shfl_xor_sync(FULL, val[e], jl);
                    u64 mx = val[e] > o ? val[e] : o;
                    u64 mn = val[e] > o ? o : val[e];
                    val[e] = (iLow == dir) ? mx : mn;
                }
            }
        }
        // register tail: j = 2..1
        #pragma unroll
        for (int j = 2; j > 0; j >>= 1) {
            #pragma unroll
            for (int e = 0; e < EPT; e++) {
                if ((e & j) == 0) {
                    int f = e | j;
                    u64 x = val[e], y = val[f];
                    bool sw = dir ? (x < y) : (x > y);
                    if (sw) { val[e] = y; val[f] = x; }
                }
            }
        }
    }
    #pragma unroll
    for (int e = 0; e < EPT; e++) skey[base + e] = val[e];
    __syncthreads();

    // ============== pipelined lazy greedy (1 barrier per batch) ==============
    int npicks_pp = 0;     // P_{n-2}: pick count through batch n-2 (all threads)
    int npicks_w  = 0;     // exact pick count (warp0 lanes)
    u32 acc_prev  = 0;     // warp0: accept mask of batch n-1

    #pragma unroll 1
    for (int n = 0;; n++) {
        int rb = n * 32;
        if (rb >= NBOX) break;
        if (n >= 2) npicks_pp = min(npicks_pp + (int)__popc(sacc3[(n - 2) % 3]), MAXDET);
        if (npicks_pp >= MAXDET) break;

        // stage batch-n candidates (all warps, broadcast LDS)
        u64 kkey = skey[rb + lane];
        if (__shfl_sync(FULL, kkey, 0) == 0ULL) break;   // rank rb invalid => done
        int cidx = (int)(~(u32)kkey) & (NBOX - 1);
        float4 myb = sbox[cidx];
        float  mya = ciou_area(myb);
        u32 vmask = __ballot_sync(FULL, kkey != 0ULL);

        const int par2 = n & 1, par3 = n % 3;

        if (warp < 4) {
            // (b) in-batch 32x32 overlap matrix
            u32 bits8 = 0;
            #pragma unroll
            for (int q = 0; q < 8; q++) {
                int c = warp * 8 + q;
                float4 ob;
                ob.x = __shfl_sync(FULL, myb.x, c);
                ob.y = __shfl_sync(FULL, myb.y, c);
                ob.z = __shfl_sync(FULL, myb.z, c);
                ob.w = __shfl_sync(FULL, myb.w, c);
                float oa = __shfl_sync(FULL, mya, c);
                bool ov = inter_of(myb, ob) > mya + oa;
                bits8 |= (ov ? 1u : 0u) << q;
            }
            smat8[par2 * 128 + lane * 4 + warp] = (unsigned char)bits8;
        } else if (warp < 12) {
            // (a) candidates vs picks through batch n-2 (lag-2, race-free)
            bool dead = false;
            for (int j = warp - 4; j < npicks_pp; j += 8) {
                float4 pb = pbox[j];
                dead |= inter_of(pb, myb) > pca[j] + mya;
            }
            u32 bal = __ballot_sync(FULL, dead);
            if (lane == 0) sdead[par2 * 8 + (warp - 4)] = bal;
        } else if (rb + 32 < NBOX) {
            // (x) cross overlap: batch n candidates vs batch n+1 candidates
            u64 k2 = skey[rb + 32 + lane];
            int ci2 = (int)(~(u32)k2) & (NBOX - 1);
            float4 b2 = sbox[ci2];
            float  a2 = ciou_area(b2);
            u32 bits8 = 0;
            #pragma unroll
            for (int q = 0; q < 8; q++) {
                int c = (warp - 12) * 8 + q;
                u64 kc = skey[rb + c];                   // broadcast
                int cc = (int)(~(u32)kc) & (NBOX - 1);
                float4 cbx = sbox[cc];
                float  ca = ciou_area(cbx);
                bool ov = inter_of(b2, cbx) > a2 + ca;
                bits8 |= (ov ? 1u : 0u) << q;
            }
            xmat8[par3 * 128 + lane * 4 + (warp - 12)] = (unsigned char)bits8;
        }
        __syncthreads();   // single barrier per batch

        // walk_n (warp0 only) — overlaps batch n+1 phases in other warps
        if (warp == 0) {
            const u32* sd = sdead + par2 * 8;
            u32 deadP = (sd[0] | sd[1]) | (sd[2] | sd[3]);
            deadP |= (sd[4] | sd[5]) | (sd[6] | sd[7]);
            u32 elig = vmask & ~deadP;

            if (n >= 1) {      // fold in batch n-1 picks via cross matrix
                const u32* xr = (const u32*)(xmat8 + ((n - 1) % 3) * 128);
                u32 dx = 0;
                #pragma unroll
                for (int j = 0; j < 32; j++)
                    dx |= ((xr[j] & acc_prev) ? 1u : 0u) << j;
                elig &= ~dx;
            }

            u32 rows[32];
            const u32* sm = (const u32*)(smat8 + par2 * 128);
            #pragma unroll
            for (int j = 0; j < 32; j++) rows[j] = sm[j];
            u32 acc = 0;
            #pragma unroll
            for (int j = 0; j < 32; j++) {
                bool take = ((elig >> j) & 1u) && ((acc & rows[j]) == 0u);
                acc |= (take ? 1u : 0u) << j;
            }
            if (lane == 0) sacc3[par3] = acc;

            if ((acc >> lane) & 1u) {                   // lane == candidate
                int slot = npicks_w + __popc(acc & ((1u << lane) - 1u));
                if (slot < MAXDET) {
                    pbox[slot] = myb;
                    pca[slot]  = mya;
                    float* row = outr + slot * 5;
                    row[1] = myb.x; row[2] = myb.y; row[3] = myb.z; row[4] = myb.w;
                    if (write_mask) outm[slot] = 1.f;
                }
            }
            npicks_w += __popc(acc);
            acc_prev = acc;
        }
    }
}

extern "C" void kernel_launch(void* const* d_in, const int* in_sizes, int n_in,
                              void* d_out, int out_size) {
    const float* boxes  = (const float*)d_in[0];   // [8,2048,4] f32
    const float* scores = (const float*)d_in[1];   // [8,2048]   f32
    float* out = (float*)d_out;
    int write_mask = (out_size >= BATCH * MAXDET * 5 + BATCH * MAXDET) ? 1 : 0;

    static int attr_done = 0;
    if (!attr_done) {
        cudaFuncSetAttribute(nms_kernel,
                             cudaFuncAttributeMaxDynamicSharedMemorySize,
                             SMEM_BYTES);
        attr_done = 1;
    }
    nms_kernel<<<BATCH, THREADS, SMEM_BYTES>>>(boxes, scores, out, write_mask);
}